// round 7
// baseline (speedup 1.0000x reference)
#include <cuda_runtime.h>
#include <cstdint>

#define N_TOK 8192
#define EMB 1024
#define HID 4096
#define NE 8

// ---------------- device scratch (no allocations allowed) ----------------
__device__ float g_H[(size_t)N_TOK * EMB];        // router hidden
__device__ float g_hidden[(size_t)N_TOK * HID];   // expert hidden (permuted rows)
__device__ int   g_chosen[N_TOK];
__device__ int   g_counts[NE];
__device__ int   g_offsets[NE + 1];
__device__ int   g_cursor[NE];
__device__ int   g_perm[N_TOK];

// ---------------- helpers ----------------
__device__ __forceinline__ uint32_t smem_u32(const void* p) {
    uint32_t a;
    asm("{ .reg .u64 t; cvta.to.shared.u64 t, %1; cvt.u32.u64 %0, t; }" : "=r"(a) : "l"(p));
    return a;
}
__device__ __forceinline__ uint32_t lds_u32(uint32_t addr) {
    uint32_t v;
    asm volatile("ld.shared.b32 %0, [%1];" : "=r"(v) : "r"(addr));
    return v;
}
__device__ __forceinline__ void mma_bf16(float* c, const uint32_t* a, const uint32_t* b) {
    asm volatile(
        "mma.sync.aligned.m16n8k16.row.col.f32.bf16.bf16.f32 "
        "{%0,%1,%2,%3}, {%4,%5,%6,%7}, {%8,%9}, {%0,%1,%2,%3};"
        : "+f"(c[0]), "+f"(c[1]), "+f"(c[2]), "+f"(c[3])
        : "r"(a[0]), "r"(a[1]), "r"(a[2]), "r"(a[3]), "r"(b[0]), "r"(b[1]));
}
__device__ __forceinline__ uint32_t bf16x2(float x, float y) {
    uint32_t r;
    asm("cvt.rn.bf16x2.f32 %0, %1, %2;" : "=r"(r) : "f"(y), "f"(x));
    return r;
}
__device__ __forceinline__ void split_pair(float x, float y, uint32_t& hi, uint32_t& lo) {
    hi = bf16x2(x, y);
    float hx = __uint_as_float(hi << 16);
    float hy = __uint_as_float(hi & 0xFFFF0000u);
    lo = bf16x2(x - hx, y - hy);
}
__device__ __forceinline__ void sts_v4(uint32_t addr, uint32_t a, uint32_t b, uint32_t c, uint32_t d) {
    asm volatile("st.shared.v4.b32 [%0], {%1,%2,%3,%4};" :: "r"(addr), "r"(a), "r"(b), "r"(c), "r"(d) : "memory");
}
__device__ __forceinline__ void sts_v2(uint32_t addr, uint32_t a, uint32_t b) {
    asm volatile("st.shared.v2.b32 [%0], {%1,%2};" :: "r"(addr), "r"(a), "r"(b) : "memory");
}

// packed f32x2 (router GEMM)
__device__ __forceinline__ uint64_t pk2(float x, float y) {
    uint64_t r;
    asm("mov.b64 %0, {%1, %2};" : "=l"(r) : "f"(x), "f"(y));
    return r;
}
__device__ __forceinline__ void ffma2(uint64_t& d, uint64_t a, uint64_t b) {
    asm("fma.rn.f32x2 %0, %1, %2, %0;" : "+l"(d) : "l"(a), "l"(b));
}
__device__ __forceinline__ void unpk2(uint64_t v, float& x, float& y) {
    asm("mov.b64 {%0, %1}, %2;" : "=f"(x), "=f"(y) : "l"(v));
}
#define FFMA2_KK_STEP(accp, a, b) do {                                   \
    uint64_t _a2[4], _b2[8];                                             \
    _a2[0] = pk2((a)[0], (a)[1]); _a2[1] = pk2((a)[2], (a)[3]);          \
    _a2[2] = pk2((a)[4], (a)[5]); _a2[3] = pk2((a)[6], (a)[7]);          \
    _b2[0] = pk2((b)[0], (b)[0]); _b2[1] = pk2((b)[1], (b)[1]);          \
    _b2[2] = pk2((b)[2], (b)[2]); _b2[3] = pk2((b)[3], (b)[3]);          \
    _b2[4] = pk2((b)[4], (b)[4]); _b2[5] = pk2((b)[5], (b)[5]);          \
    _b2[6] = pk2((b)[6], (b)[6]); _b2[7] = pk2((b)[7], (b)[7]);          \
    _Pragma("unroll")                                                    \
    for (int _i = 0; _i < 4; _i++)                                       \
        _Pragma("unroll")                                                \
        for (int _j = 0; _j < 8; _j++) ffma2((accp)[_i][_j], _a2[_i], _b2[_j]); \
} while (0)

// SMEM stage layout (bf16, row stride 40 elems = 80 B, conflict-free):
// A_hi [0,10240) | A_lo [10240,20480) | B_hi [20480,30720) | B_lo [30720,40960)
#define RS 40
#define OFF_ALO 10240u
#define OFF_BHI 20480u
#define OFF_BLO 30720u
#define STAGE 40960u
#define FFN_SMEM (2 * 40960)

// ============================================================================
// bf16x3 mma.sync FFN GEMM, 2-stage pipelined. Tile 128x128, BK=32,
// 256 thr = 8 warps (4m x 2n), warp 32x64. Direct-LDS fragments (verified).
// ============================================================================
template <int NTOT, int KTOT, bool GATHER, bool RELU, bool SCATTER>
__global__ __launch_bounds__(256, 2) void ffn_mma(
    const float* __restrict__ A, const float* __restrict__ Bw,
    const float* __restrict__ biasw, float* __restrict__ C)
{
    extern __shared__ __align__(16) uint8_t smem[];
    const int e = blockIdx.z;
    const int start = g_offsets[e], end = g_offsets[e + 1];
    const int m0 = start + blockIdx.x * 128;
    if (m0 >= end) return;
    const int n0 = blockIdx.y * 128;
    const float* Bm = Bw + (size_t)e * KTOT * NTOT;
    const uint32_t sb = smem_u32(smem);

    const int tid = threadIdx.x, wid = tid >> 5, lane = tid & 31;
    const int wm = wid & 3, wn = wid >> 2, qid = lane >> 2, tig = lane & 3;

    // A loader: row = tid>>1, k-half = (tid&1)*16
    const int ar = tid >> 1;
    const int akc = (tid & 1) * 16;
    int rld = m0 + ar;
    int rc = (rld < end) ? rld : start;
    int grow = GATHER ? g_perm[rc] : rc;
    const float* Ap = A + (size_t)grow * KTOT + akc;
    const uint32_t a_sts = (uint32_t)(ar * RS + akc) * 2;

    // B loader: warp -> 4 k-rows, lane -> n in 32-col group; col group j via +j*2560
    const int bk = wid * 4;
    const int bn = lane;
    const float* Bp = Bm + n0 + bn;
    const uint32_t b_sts0 = (uint32_t)(bn * RS + bk) * 2;

    // fragment LDS bases (immediate offsets used for mt/nt/ks)
    const uint32_t aoff0 = (uint32_t)((wm * 32 + qid) * RS + tig * 2) * 2;
    const uint32_t boff0 = OFF_BHI + (uint32_t)((wn * 64 + qid) * RS + tig * 2) * 2;

    float acc[2][8][4];
#pragma unroll
    for (int mt = 0; mt < 2; mt++)
#pragma unroll
        for (int nt = 0; nt < 8; nt++)
#pragma unroll
            for (int i = 0; i < 4; i++) acc[mt][nt][i] = 0.f;

    float4 av[4];
    float bv[4][4];
    const int NC = KTOT / 32;

    // ---- LDG chunk 0 ----
#pragma unroll
    for (int i = 0; i < 4; i++) av[i] = *(const float4*)(Ap + 4 * i);
#pragma unroll
    for (int i = 0; i < 4; i++) {
        const float* rowp = Bp + (size_t)(bk + i) * NTOT;
#pragma unroll
        for (int j = 0; j < 4; j++) bv[i][j] = rowp[32 * j];
    }
    // ---- split + STS stage 0 ----
    {
        uint32_t h[8], l[8];
#pragma unroll
        for (int i = 0; i < 4; i++) {
            split_pair(av[i].x, av[i].y, h[2 * i + 0], l[2 * i + 0]);
            split_pair(av[i].z, av[i].w, h[2 * i + 1], l[2 * i + 1]);
        }
        sts_v4(sb + a_sts, h[0], h[1], h[2], h[3]);
        sts_v4(sb + a_sts + 16, h[4], h[5], h[6], h[7]);
        sts_v4(sb + OFF_ALO + a_sts, l[0], l[1], l[2], l[3]);
        sts_v4(sb + OFF_ALO + a_sts + 16, l[4], l[5], l[6], l[7]);
#pragma unroll
        for (int j = 0; j < 4; j++) {
            uint32_t bh0, bl0, bh1, bl1;
            split_pair(bv[0][j], bv[1][j], bh0, bl0);
            split_pair(bv[2][j], bv[3][j], bh1, bl1);
            sts_v2(sb + OFF_BHI + b_sts0 + j * 2560, bh0, bh1);
            sts_v2(sb + OFF_BLO + b_sts0 + j * 2560, bl0, bl1);
        }
    }
    __syncthreads();

#pragma unroll 1
    for (int kc = 0; kc < NC; kc++) {
        // LDG chunk kc+1 (latency covered by compute below)
        if (kc + 1 < NC) {
            const int k0 = (kc + 1) * 32;
#pragma unroll
            for (int i = 0; i < 4; i++) av[i] = *(const float4*)(Ap + k0 + 4 * i);
#pragma unroll
            for (int i = 0; i < 4; i++) {
                const float* rowp = Bp + (size_t)(k0 + bk + i) * NTOT;
#pragma unroll
                for (int j = 0; j < 4; j++) bv[i][j] = rowp[32 * j];
            }
        }
        // compute chunk kc from stage kc&1
        const uint32_t cur = sb + (uint32_t)(kc & 1) * STAGE;
#pragma unroll
        for (int ks = 0; ks < 2; ks++) {
            uint32_t ah[2][4], al[2][4];
#pragma unroll
            for (int mt = 0; mt < 2; mt++) {
                const uint32_t ab = cur + aoff0 + mt * 1280 + ks * 32;
                ah[mt][0] = lds_u32(ab);
                ah[mt][1] = lds_u32(ab + 8 * RS * 2);
                ah[mt][2] = lds_u32(ab + 16);
                ah[mt][3] = lds_u32(ab + 8 * RS * 2 + 16);
                al[mt][0] = lds_u32(ab + OFF_ALO);
                al[mt][1] = lds_u32(ab + OFF_ALO + 8 * RS * 2);
                al[mt][2] = lds_u32(ab + OFF_ALO + 16);
                al[mt][3] = lds_u32(ab + OFF_ALO + 8 * RS * 2 + 16);
            }
#pragma unroll
            for (int nt = 0; nt < 8; nt++) {
                const uint32_t bb = cur + boff0 + nt * 640 + ks * 32;
                uint32_t bh[2], bl[2];
                bh[0] = lds_u32(bb);
                bh[1] = lds_u32(bb + 16);
                bl[0] = lds_u32(bb + (OFF_BLO - OFF_BHI));
                bl[1] = lds_u32(bb + (OFF_BLO - OFF_BHI) + 16);
#pragma unroll
                for (int mt = 0; mt < 2; mt++) {
                    mma_bf16(acc[mt][nt], ah[mt], bh);
                    mma_bf16(acc[mt][nt], ah[mt], bl);
                    mma_bf16(acc[mt][nt], al[mt], bh);
                }
            }
        }
        // split + STS chunk kc+1 into the other stage
        if (kc + 1 < NC) {
            const uint32_t nxt = sb + (uint32_t)((kc + 1) & 1) * STAGE;
            uint32_t h[8], l[8];
#pragma unroll
            for (int i = 0; i < 4; i++) {
                split_pair(av[i].x, av[i].y, h[2 * i + 0], l[2 * i + 0]);
                split_pair(av[i].z, av[i].w, h[2 * i + 1], l[2 * i + 1]);
            }
            sts_v4(nxt + a_sts, h[0], h[1], h[2], h[3]);
            sts_v4(nxt + a_sts + 16, h[4], h[5], h[6], h[7]);
            sts_v4(nxt + OFF_ALO + a_sts, l[0], l[1], l[2], l[3]);
            sts_v4(nxt + OFF_ALO + a_sts + 16, l[4], l[5], l[6], l[7]);
#pragma unroll
            for (int j = 0; j < 4; j++) {
                uint32_t bh0, bl0, bh1, bl1;
                split_pair(bv[0][j], bv[1][j], bh0, bl0);
                split_pair(bv[2][j], bv[3][j], bh1, bl1);
                sts_v2(nxt + OFF_BHI + b_sts0 + j * 2560, bh0, bh1);
                sts_v2(nxt + OFF_BLO + b_sts0 + j * 2560, bl0, bl1);
            }
        }
        __syncthreads();
    }

    // ---- epilogue (verified) ----
    const float* bs = biasw + (size_t)e * NTOT;
    const int trow = qid, tcol = tig * 2;
    float2 bb2[8];
#pragma unroll
    for (int nt = 0; nt < 8; nt++) {
        int col = n0 + wn * 64 + nt * 8 + tcol;
        bb2[nt] = *(const float2*)(bs + col);
    }
#pragma unroll
    for (int mt = 0; mt < 2; mt++) {
        int r0 = m0 + wm * 32 + mt * 16 + trow;
        int r1 = r0 + 8;
        bool v0 = r0 < end, v1 = r1 < end;
        int c0 = SCATTER ? (v0 ? g_perm[r0] : 0) : r0;
        int c1 = SCATTER ? (v1 ? g_perm[r1] : 0) : r1;
        float* p0 = C + (size_t)c0 * NTOT + n0 + wn * 64 + tcol;
        float* p1 = C + (size_t)c1 * NTOT + n0 + wn * 64 + tcol;
#pragma unroll
        for (int nt = 0; nt < 8; nt++) {
            float2 o0, o1;
            o0.x = acc[mt][nt][0] + bb2[nt].x;
            o0.y = acc[mt][nt][1] + bb2[nt].y;
            o1.x = acc[mt][nt][2] + bb2[nt].x;
            o1.y = acc[mt][nt][3] + bb2[nt].y;
            if (RELU) {
                o0.x = fmaxf(o0.x, 0.f); o0.y = fmaxf(o0.y, 0.f);
                o1.x = fmaxf(o1.x, 0.f); o1.y = fmaxf(o1.y, 0.f);
            }
            if (v0) *(float2*)(p0 + nt * 8) = o0;
            if (v1) *(float2*)(p1 + nt * 8) = o1;
        }
    }
}

// ---------------- router GEMM (exact fp32, FFMA2; verified round 6) ----------------
__global__ __launch_bounds__(256, 2)
void sgemm_router(const float* __restrict__ A, const float* __restrict__ B,
                  const float* __restrict__ bias)
{
    const int K = EMB, N = EMB;
    __shared__ float As[8][128];
    __shared__ float Bs[8][128];
    const int tid = threadIdx.x;
    const int m0 = blockIdx.x * 128;
    const int n0 = blockIdx.y * 128;
    const int arow = tid >> 1;
    const int acol = (tid & 1) * 4;
    const int brow = tid >> 5;
    const int bcol = (tid & 31) * 4;
    const float* Ap = A + (size_t)(m0 + arow) * K + acol;
    const float* Bp = B + (size_t)brow * N + n0 + bcol;
    const int ty = (tid >> 4) * 8;
    const int tx = (tid & 15) * 8;
    uint64_t accp[4][8];
#pragma unroll
    for (int i = 0; i < 4; i++)
#pragma unroll
        for (int j = 0; j < 8; j++) accp[i][j] = 0ull;

    for (int k0 = 0; k0 < K; k0 += 8) {
        float4 av = *(const float4*)(Ap + k0);
        float4 bv = *(const float4*)(Bp + (size_t)k0 * N);
        As[acol + 0][arow] = av.x;
        As[acol + 1][arow] = av.y;
        As[acol + 2][arow] = av.z;
        As[acol + 3][arow] = av.w;
        *(float4*)&Bs[brow][bcol] = bv;
        __syncthreads();
#pragma unroll
        for (int kk = 0; kk < 8; kk++) {
            float a[8], b[8];
            *(float4*)&a[0] = *(const float4*)&As[kk][ty];
            *(float4*)&a[4] = *(const float4*)&As[kk][ty + 4];
            *(float4*)&b[0] = *(const float4*)&Bs[kk][tx];
            *(float4*)&b[4] = *(const float4*)&Bs[kk][tx + 4];
            FFMA2_KK_STEP(accp, a, b);
        }
        __syncthreads();
    }
    float acc[8][8];
#pragma unroll
    for (int i2 = 0; i2 < 4; i2++)
#pragma unroll
        for (int j = 0; j < 8; j++) unpk2(accp[i2][j], acc[2 * i2][j], acc[2 * i2 + 1][j]);
#pragma unroll
    for (int i = 0; i < 8; i++) {
        float* Cp = g_H + (size_t)(m0 + ty + i) * N + n0 + tx;
#pragma unroll
        for (int j = 0; j < 8; j += 4) {
            float4 v;
            v.x = fmaxf(acc[i][j + 0] + bias[n0 + tx + j + 0], 0.f);
            v.y = fmaxf(acc[i][j + 1] + bias[n0 + tx + j + 1], 0.f);
            v.z = fmaxf(acc[i][j + 2] + bias[n0 + tx + j + 2], 0.f);
            v.w = fmaxf(acc[i][j + 3] + bias[n0 + tx + j + 3], 0.f);
            *(float4*)(Cp + j) = v;
        }
    }
}

// ---------------- router argmax + token sort (verified) ----------------
__global__ void init_counts() { if (threadIdx.x < NE) g_counts[threadIdx.x] = 0; }

__global__ __launch_bounds__(256)
void router_argmax(const float* __restrict__ Wr2, const float* __restrict__ br2)
{
    int gid = blockIdx.x * blockDim.x + threadIdx.x;
    int t = gid >> 5;
    int lane = gid & 31;
    if (t >= N_TOK) return;
    const float* h = g_H + (size_t)t * EMB;
    float acc[NE];
#pragma unroll
    for (int e = 0; e < NE; e++) acc[e] = 0.f;
    for (int i = lane; i < EMB; i += 32) {
        float hv = h[i];
        const float4 w0 = *(const float4*)(Wr2 + (size_t)i * NE);
        const float4 w1 = *(const float4*)(Wr2 + (size_t)i * NE + 4);
        acc[0] = fmaf(hv, w0.x, acc[0]);
        acc[1] = fmaf(hv, w0.y, acc[1]);
        acc[2] = fmaf(hv, w0.z, acc[2]);
        acc[3] = fmaf(hv, w0.w, acc[3]);
        acc[4] = fmaf(hv, w1.x, acc[4]);
        acc[5] = fmaf(hv, w1.y, acc[5]);
        acc[6] = fmaf(hv, w1.z, acc[6]);
        acc[7] = fmaf(hv, w1.w, acc[7]);
    }
#pragma unroll
    for (int off = 16; off > 0; off >>= 1)
#pragma unroll
        for (int e = 0; e < NE; e++)
            acc[e] += __shfl_xor_sync(0xffffffffu, acc[e], off);
    if (lane == 0) {
        int best = 0;
        float bv = acc[0] + br2[0];
#pragma unroll
        for (int e = 1; e < NE; e++) {
            float v = acc[e] + br2[e];
            if (v > bv) { bv = v; best = e; }
        }
        g_chosen[t] = best;
        atomicAdd(&g_counts[best], 1);
    }
}

__global__ void scan_offsets()
{
    if (threadIdx.x == 0 && blockIdx.x == 0) {
        int o = 0;
        for (int e = 0; e < NE; e++) {
            g_offsets[e] = o;
            g_cursor[e] = o;
            o += g_counts[e];
        }
        g_offsets[NE] = o;
    }
}

__global__ void scatter_tokens()
{
    int t = blockIdx.x * blockDim.x + threadIdx.x;
    if (t >= N_TOK) return;
    int e = g_chosen[t];
    int pos = atomicAdd(&g_cursor[e], 1);
    g_perm[pos] = t;
}

// ---------------- launch ----------------
extern "C" void kernel_launch(void* const* d_in, const int* in_sizes, int n_in,
                              void* d_out, int out_size)
{
    const float* x   = (const float*)d_in[0];
    const float* Wr1 = (const float*)d_in[1];
    const float* br1 = (const float*)d_in[2];
    const float* Wr2 = (const float*)d_in[3];
    const float* br2 = (const float*)d_in[4];
    const float* W1  = (const float*)d_in[5];
    const float* b1  = (const float*)d_in[6];
    const float* W2  = (const float*)d_in[7];
    const float* b2  = (const float*)d_in[8];
    float* out = (float*)d_out;

    auto* kFfn1 = ffn_mma<HID, EMB, true, true, false>;
    auto* kFfn2 = ffn_mma<EMB, HID, false, false, true>;
    cudaFuncSetAttribute(kFfn1, cudaFuncAttributeMaxDynamicSharedMemorySize, FFN_SMEM);
    cudaFuncSetAttribute(kFfn2, cudaFuncAttributeMaxDynamicSharedMemorySize, FFN_SMEM);

    init_counts<<<1, 32>>>();
    sgemm_router<<<dim3(N_TOK / 128, EMB / 128), 256>>>(x, Wr1, br1);
    router_argmax<<<(N_TOK * 32) / 256, 256>>>(Wr2, br2);
    scan_offsets<<<1, 1>>>();
    scatter_tokens<<<N_TOK / 256, 256>>>();
    kFfn1<<<dim3(N_TOK / 128, HID / 128, NE), 256, FFN_SMEM>>>(x, W1, b1, g_hidden);
    kFfn2<<<dim3(N_TOK / 128, EMB / 128, NE), 256, FFN_SMEM>>>(g_hidden, W2, b2, out);
}

// round 9
// speedup vs baseline: 6.0694x; 6.0694x over previous
#include <cuda_runtime.h>
#include <cstdint>

#define N_TOK 8192
#define EMB 1024
#define HID 4096
#define NE 8

// ---------------- device scratch (no allocations allowed) ----------------
// NOTE: these symbols must ONLY be referenced inside device code. Passing them
// as kernel arguments from host code yields the HOST shadow address (ATS makes
// the resulting writes silently land in host memory) — root cause of the
// round-3/4/8 failures and the round-5/7 slowness.
__device__ float g_H[(size_t)N_TOK * EMB];        // router hidden
__device__ float g_hidden[(size_t)N_TOK * HID];   // expert hidden (permuted rows)
__device__ int   g_chosen[N_TOK];
__device__ int   g_counts[NE];
__device__ int   g_offsets[NE + 1];
__device__ int   g_cursor[NE];
__device__ int   g_perm[N_TOK];

// ---------------- helpers ----------------
__device__ __forceinline__ uint32_t smem_u32(const void* p) {
    uint32_t a;
    asm("{ .reg .u64 t; cvta.to.shared.u64 t, %1; cvt.u32.u64 %0, t; }" : "=r"(a) : "l"(p));
    return a;
}
__device__ __forceinline__ uint32_t lds_u32(uint32_t addr) {
    uint32_t v;
    asm volatile("ld.shared.b32 %0, [%1];" : "=r"(v) : "r"(addr));
    return v;
}
__device__ __forceinline__ void mma_bf16(float* c, const uint32_t* a, const uint32_t* b) {
    asm volatile(
        "mma.sync.aligned.m16n8k16.row.col.f32.bf16.bf16.f32 "
        "{%0,%1,%2,%3}, {%4,%5,%6,%7}, {%8,%9}, {%0,%1,%2,%3};"
        : "+f"(c[0]), "+f"(c[1]), "+f"(c[2]), "+f"(c[3])
        : "r"(a[0]), "r"(a[1]), "r"(a[2]), "r"(a[3]), "r"(b[0]), "r"(b[1]));
}
__device__ __forceinline__ uint32_t bf16x2(float x, float y) {
    uint32_t r;
    asm("cvt.rn.bf16x2.f32 %0, %1, %2;" : "=r"(r) : "f"(y), "f"(x));
    return r;
}
__device__ __forceinline__ void split_pair(float x, float y, uint32_t& hi, uint32_t& lo) {
    hi = bf16x2(x, y);
    float hx = __uint_as_float(hi << 16);
    float hy = __uint_as_float(hi & 0xFFFF0000u);
    lo = bf16x2(x - hx, y - hy);
}
__device__ __forceinline__ void sts_v4(uint32_t addr, uint32_t a, uint32_t b, uint32_t c, uint32_t d) {
    asm volatile("st.shared.v4.b32 [%0], {%1,%2,%3,%4};" :: "r"(addr), "r"(a), "r"(b), "r"(c), "r"(d) : "memory");
}
__device__ __forceinline__ void sts_v2(uint32_t addr, uint32_t a, uint32_t b) {
    asm volatile("st.shared.v2.b32 [%0], {%1,%2};" :: "r"(addr), "r"(a), "r"(b) : "memory");
}

// packed f32x2 (router GEMM)
__device__ __forceinline__ uint64_t pk2(float x, float y) {
    uint64_t r;
    asm("mov.b64 %0, {%1, %2};" : "=l"(r) : "f"(x), "f"(y));
    return r;
}
__device__ __forceinline__ void ffma2(uint64_t& d, uint64_t a, uint64_t b) {
    asm("fma.rn.f32x2 %0, %1, %2, %0;" : "+l"(d) : "l"(a), "l"(b));
}
__device__ __forceinline__ void unpk2(uint64_t v, float& x, float& y) {
    asm("mov.b64 {%0, %1}, %2;" : "=f"(x), "=f"(y) : "l"(v));
}
#define FFMA2_KK_STEP(accp, a, b) do {                                   \
    uint64_t _a2[4], _b2[8];                                             \
    _a2[0] = pk2((a)[0], (a)[1]); _a2[1] = pk2((a)[2], (a)[3]);          \
    _a2[2] = pk2((a)[4], (a)[5]); _a2[3] = pk2((a)[6], (a)[7]);          \
    _b2[0] = pk2((b)[0], (b)[0]); _b2[1] = pk2((b)[1], (b)[1]);          \
    _b2[2] = pk2((b)[2], (b)[2]); _b2[3] = pk2((b)[3], (b)[3]);          \
    _b2[4] = pk2((b)[4], (b)[4]); _b2[5] = pk2((b)[5], (b)[5]);          \
    _b2[6] = pk2((b)[6], (b)[6]); _b2[7] = pk2((b)[7], (b)[7]);          \
    _Pragma("unroll")                                                    \
    for (int _i = 0; _i < 4; _i++)                                       \
        _Pragma("unroll")                                                \
        for (int _j = 0; _j < 8; _j++) ffma2((accp)[_i][_j], _a2[_i], _b2[_j]); \
} while (0)

// SMEM stage layout (bf16, row stride 40 elems = 80 B, conflict-free):
// A_hi [0,10240) | A_lo [10240,20480) | B_hi [20480,30720) | B_lo [30720,40960)
#define RS 40
#define OFF_ALO 10240u
#define OFF_BHI 20480u
#define OFF_BLO 30720u
#define STAGE 40960u
#define FFN_SMEM (2 * 40960)

// ============================================================================
// bf16x3 mma.sync FFN GEMM, 2-stage pipelined. Tile 128x128, BK=32,
// 256 thr = 8 warps (4m x 2n), warp 32x64. Direct-LDS fragments (verified R5/R7).
// SRC_HIDDEN / DST_HIDDEN select g_hidden via the DEVICE symbol (correct addr).
// ============================================================================
template <int NTOT, int KTOT, bool GATHER, bool RELU, bool SCATTER,
          bool SRC_HIDDEN, bool DST_HIDDEN>
__global__ __launch_bounds__(256, 2) void ffn_mma(
    const float* __restrict__ Ain, const float* __restrict__ Bw,
    const float* __restrict__ biasw, float* __restrict__ Cout)
{
    extern __shared__ __align__(16) uint8_t smem[];
    const float* A = SRC_HIDDEN ? (const float*)g_hidden : Ain;
    float* C = DST_HIDDEN ? (float*)g_hidden : Cout;

    const int e = blockIdx.z;
    const int start = g_offsets[e], end = g_offsets[e + 1];
    const int m0 = start + blockIdx.x * 128;
    if (m0 >= end) return;
    const int n0 = blockIdx.y * 128;
    const float* Bm = Bw + (size_t)e * KTOT * NTOT;
    const uint32_t sb = smem_u32(smem);

    const int tid = threadIdx.x, wid = tid >> 5, lane = tid & 31;
    const int wm = wid & 3, wn = wid >> 2, qid = lane >> 2, tig = lane & 3;

    // A loader: row = tid>>1, k-half = (tid&1)*16
    const int ar = tid >> 1;
    const int akc = (tid & 1) * 16;
    int rld = m0 + ar;
    int rc = (rld < end) ? rld : start;
    int grow = GATHER ? g_perm[rc] : rc;
    const float* Ap = A + (size_t)grow * KTOT + akc;
    const uint32_t a_sts = (uint32_t)(ar * RS + akc) * 2;

    // B loader: warp -> 4 k-rows, lane -> n in 32-col group; col group j via +j*2560
    const int bk = wid * 4;
    const int bn = lane;
    const float* Bp = Bm + n0 + bn;
    const uint32_t b_sts0 = (uint32_t)(bn * RS + bk) * 2;

    // fragment LDS bases
    const uint32_t aoff0 = (uint32_t)((wm * 32 + qid) * RS + tig * 2) * 2;
    const uint32_t boff0 = OFF_BHI + (uint32_t)((wn * 64 + qid) * RS + tig * 2) * 2;

    float acc[2][8][4];
#pragma unroll
    for (int mt = 0; mt < 2; mt++)
#pragma unroll
        for (int nt = 0; nt < 8; nt++)
#pragma unroll
            for (int i = 0; i < 4; i++) acc[mt][nt][i] = 0.f;

    float4 av[4];
    float bv[4][4];
    const int NC = KTOT / 32;

    // ---- LDG chunk 0 ----
#pragma unroll
    for (int i = 0; i < 4; i++) av[i] = *(const float4*)(Ap + 4 * i);
#pragma unroll
    for (int i = 0; i < 4; i++) {
        const float* rowp = Bp + (size_t)(bk + i) * NTOT;
#pragma unroll
        for (int j = 0; j < 4; j++) bv[i][j] = rowp[32 * j];
    }
    // ---- split + STS stage 0 ----
    {
        uint32_t h[8], l[8];
#pragma unroll
        for (int i = 0; i < 4; i++) {
            split_pair(av[i].x, av[i].y, h[2 * i + 0], l[2 * i + 0]);
            split_pair(av[i].z, av[i].w, h[2 * i + 1], l[2 * i + 1]);
        }
        sts_v4(sb + a_sts, h[0], h[1], h[2], h[3]);
        sts_v4(sb + a_sts + 16, h[4], h[5], h[6], h[7]);
        sts_v4(sb + OFF_ALO + a_sts, l[0], l[1], l[2], l[3]);
        sts_v4(sb + OFF_ALO + a_sts + 16, l[4], l[5], l[6], l[7]);
#pragma unroll
        for (int j = 0; j < 4; j++) {
            uint32_t bh0, bl0, bh1, bl1;
            split_pair(bv[0][j], bv[1][j], bh0, bl0);
            split_pair(bv[2][j], bv[3][j], bh1, bl1);
            sts_v2(sb + OFF_BHI + b_sts0 + j * 2560, bh0, bh1);
            sts_v2(sb + OFF_BLO + b_sts0 + j * 2560, bl0, bl1);
        }
    }
    __syncthreads();

#pragma unroll 1
    for (int kc = 0; kc < NC; kc++) {
        // LDG chunk kc+1 (latency covered by compute below)
        if (kc + 1 < NC) {
            const int k0 = (kc + 1) * 32;
#pragma unroll
            for (int i = 0; i < 4; i++) av[i] = *(const float4*)(Ap + k0 + 4 * i);
#pragma unroll
            for (int i = 0; i < 4; i++) {
                const float* rowp = Bp + (size_t)(k0 + bk + i) * NTOT;
#pragma unroll
                for (int j = 0; j < 4; j++) bv[i][j] = rowp[32 * j];
            }
        }
        // compute chunk kc from stage kc&1
        const uint32_t cur = sb + (uint32_t)(kc & 1) * STAGE;
#pragma unroll
        for (int ks = 0; ks < 2; ks++) {
            uint32_t ah[2][4], al[2][4];
#pragma unroll
            for (int mt = 0; mt < 2; mt++) {
                const uint32_t ab = cur + aoff0 + mt * 1280 + ks * 32;
                ah[mt][0] = lds_u32(ab);
                ah[mt][1] = lds_u32(ab + 8 * RS * 2);
                ah[mt][2] = lds_u32(ab + 16);
                ah[mt][3] = lds_u32(ab + 8 * RS * 2 + 16);
                al[mt][0] = lds_u32(ab + OFF_ALO);
                al[mt][1] = lds_u32(ab + OFF_ALO + 8 * RS * 2);
                al[mt][2] = lds_u32(ab + OFF_ALO + 16);
                al[mt][3] = lds_u32(ab + OFF_ALO + 8 * RS * 2 + 16);
            }
#pragma unroll
            for (int nt = 0; nt < 8; nt++) {
                const uint32_t bb = cur + boff0 + nt * 640 + ks * 32;
                uint32_t bh[2], bl[2];
                bh[0] = lds_u32(bb);
                bh[1] = lds_u32(bb + 16);
                bl[0] = lds_u32(bb + (OFF_BLO - OFF_BHI));
                bl[1] = lds_u32(bb + (OFF_BLO - OFF_BHI) + 16);
#pragma unroll
                for (int mt = 0; mt < 2; mt++) {
                    mma_bf16(acc[mt][nt], ah[mt], bh);
                    mma_bf16(acc[mt][nt], ah[mt], bl);
                    mma_bf16(acc[mt][nt], al[mt], bh);
                }
            }
        }
        // split + STS chunk kc+1 into the other stage
        if (kc + 1 < NC) {
            const uint32_t nxt = sb + (uint32_t)((kc + 1) & 1) * STAGE;
            uint32_t h[8], l[8];
#pragma unroll
            for (int i = 0; i < 4; i++) {
                split_pair(av[i].x, av[i].y, h[2 * i + 0], l[2 * i + 0]);
                split_pair(av[i].z, av[i].w, h[2 * i + 1], l[2 * i + 1]);
            }
            sts_v4(nxt + a_sts, h[0], h[1], h[2], h[3]);
            sts_v4(nxt + a_sts + 16, h[4], h[5], h[6], h[7]);
            sts_v4(nxt + OFF_ALO + a_sts, l[0], l[1], l[2], l[3]);
            sts_v4(nxt + OFF_ALO + a_sts + 16, l[4], l[5], l[6], l[7]);
#pragma unroll
            for (int j = 0; j < 4; j++) {
                uint32_t bh0, bl0, bh1, bl1;
                split_pair(bv[0][j], bv[1][j], bh0, bl0);
                split_pair(bv[2][j], bv[3][j], bh1, bl1);
                sts_v2(nxt + OFF_BHI + b_sts0 + j * 2560, bh0, bh1);
                sts_v2(nxt + OFF_BLO + b_sts0 + j * 2560, bl0, bl1);
            }
        }
        __syncthreads();
    }

    // ---- epilogue (verified) ----
    const float* bs = biasw + (size_t)e * NTOT;
    const int trow = qid, tcol = tig * 2;
    float2 bb2[8];
#pragma unroll
    for (int nt = 0; nt < 8; nt++) {
        int col = n0 + wn * 64 + nt * 8 + tcol;
        bb2[nt] = *(const float2*)(bs + col);
    }
#pragma unroll
    for (int mt = 0; mt < 2; mt++) {
        int r0 = m0 + wm * 32 + mt * 16 + trow;
        int r1 = r0 + 8;
        bool v0 = r0 < end, v1 = r1 < end;
        int c0 = SCATTER ? (v0 ? g_perm[r0] : 0) : r0;
        int c1 = SCATTER ? (v1 ? g_perm[r1] : 0) : r1;
        float* p0 = C + (size_t)c0 * NTOT + n0 + wn * 64 + tcol;
        float* p1 = C + (size_t)c1 * NTOT + n0 + wn * 64 + tcol;
#pragma unroll
        for (int nt = 0; nt < 8; nt++) {
            float2 o0, o1;
            o0.x = acc[mt][nt][0] + bb2[nt].x;
            o0.y = acc[mt][nt][1] + bb2[nt].y;
            o1.x = acc[mt][nt][2] + bb2[nt].x;
            o1.y = acc[mt][nt][3] + bb2[nt].y;
            if (RELU) {
                o0.x = fmaxf(o0.x, 0.f); o0.y = fmaxf(o0.y, 0.f);
                o1.x = fmaxf(o1.x, 0.f); o1.y = fmaxf(o1.y, 0.f);
            }
            if (v0) *(float2*)(p0 + nt * 8) = o0;
            if (v1) *(float2*)(p1 + nt * 8) = o1;
        }
    }
}

// ---------------- router GEMM (exact fp32, FFMA2; verified R6; writes g_H internally) ----------------
__global__ __launch_bounds__(256, 2)
void sgemm_router(const float* __restrict__ A, const float* __restrict__ B,
                  const float* __restrict__ bias)
{
    const int K = EMB, N = EMB;
    __shared__ float As[8][128];
    __shared__ float Bs[8][128];
    const int tid = threadIdx.x;
    const int m0 = blockIdx.x * 128;
    const int n0 = blockIdx.y * 128;
    const int arow = tid >> 1;
    const int acol = (tid & 1) * 4;
    const int brow = tid >> 5;
    const int bcol = (tid & 31) * 4;
    const float* Ap = A + (size_t)(m0 + arow) * K + acol;
    const float* Bp = B + (size_t)brow * N + n0 + bcol;
    const int ty = (tid >> 4) * 8;
    const int tx = (tid & 15) * 8;
    uint64_t accp[4][8];
#pragma unroll
    for (int i = 0; i < 4; i++)
#pragma unroll
        for (int j = 0; j < 8; j++) accp[i][j] = 0ull;

    for (int k0 = 0; k0 < K; k0 += 8) {
        float4 av = *(const float4*)(Ap + k0);
        float4 bv = *(const float4*)(Bp + (size_t)k0 * N);
        As[acol + 0][arow] = av.x;
        As[acol + 1][arow] = av.y;
        As[acol + 2][arow] = av.z;
        As[acol + 3][arow] = av.w;
        *(float4*)&Bs[brow][bcol] = bv;
        __syncthreads();
#pragma unroll
        for (int kk = 0; kk < 8; kk++) {
            float a[8], b[8];
            *(float4*)&a[0] = *(const float4*)&As[kk][ty];
            *(float4*)&a[4] = *(const float4*)&As[kk][ty + 4];
            *(float4*)&b[0] = *(const float4*)&Bs[kk][tx];
            *(float4*)&b[4] = *(const float4*)&Bs[kk][tx + 4];
            FFMA2_KK_STEP(accp, a, b);
        }
        __syncthreads();
    }
    float acc[8][8];
#pragma unroll
    for (int i2 = 0; i2 < 4; i2++)
#pragma unroll
        for (int j = 0; j < 8; j++) unpk2(accp[i2][j], acc[2 * i2][j], acc[2 * i2 + 1][j]);
#pragma unroll
    for (int i = 0; i < 8; i++) {
        float* Cp = g_H + (size_t)(m0 + ty + i) * N + n0 + tx;
#pragma unroll
        for (int j = 0; j < 8; j += 4) {
            float4 v;
            v.x = fmaxf(acc[i][j + 0] + bias[n0 + tx + j + 0], 0.f);
            v.y = fmaxf(acc[i][j + 1] + bias[n0 + tx + j + 1], 0.f);
            v.z = fmaxf(acc[i][j + 2] + bias[n0 + tx + j + 2], 0.f);
            v.w = fmaxf(acc[i][j + 3] + bias[n0 + tx + j + 3], 0.f);
            *(float4*)(Cp + j) = v;
        }
    }
}

// ---------------- router argmax + token sort (verified) ----------------
__global__ void init_counts() { if (threadIdx.x < NE) g_counts[threadIdx.x] = 0; }

__global__ __launch_bounds__(256)
void router_argmax(const float* __restrict__ Wr2, const float* __restrict__ br2)
{
    int gid = blockIdx.x * blockDim.x + threadIdx.x;
    int t = gid >> 5;
    int lane = gid & 31;
    if (t >= N_TOK) return;
    const float* h = g_H + (size_t)t * EMB;
    float acc[NE];
#pragma unroll
    for (int e = 0; e < NE; e++) acc[e] = 0.f;
    for (int i = lane; i < EMB; i += 32) {
        float hv = h[i];
        const float4 w0 = *(const float4*)(Wr2 + (size_t)i * NE);
        const float4 w1 = *(const float4*)(Wr2 + (size_t)i * NE + 4);
        acc[0] = fmaf(hv, w0.x, acc[0]);
        acc[1] = fmaf(hv, w0.y, acc[1]);
        acc[2] = fmaf(hv, w0.z, acc[2]);
        acc[3] = fmaf(hv, w0.w, acc[3]);
        acc[4] = fmaf(hv, w1.x, acc[4]);
        acc[5] = fmaf(hv, w1.y, acc[5]);
        acc[6] = fmaf(hv, w1.z, acc[6]);
        acc[7] = fmaf(hv, w1.w, acc[7]);
    }
#pragma unroll
    for (int off = 16; off > 0; off >>= 1)
#pragma unroll
        for (int e = 0; e < NE; e++)
            acc[e] += __shfl_xor_sync(0xffffffffu, acc[e], off);
    if (lane == 0) {
        int best = 0;
        float bv = acc[0] + br2[0];
#pragma unroll
        for (int e = 1; e < NE; e++) {
            float v = acc[e] + br2[e];
            if (v > bv) { bv = v; best = e; }
        }
        g_chosen[t] = best;
        atomicAdd(&g_counts[best], 1);
    }
}

__global__ void scan_offsets()
{
    if (threadIdx.x == 0 && blockIdx.x == 0) {
        int o = 0;
        for (int e = 0; e < NE; e++) {
            g_offsets[e] = o;
            g_cursor[e] = o;
            o += g_counts[e];
        }
        g_offsets[NE] = o;
    }
}

__global__ void scatter_tokens()
{
    int t = blockIdx.x * blockDim.x + threadIdx.x;
    if (t >= N_TOK) return;
    int e = g_chosen[t];
    int pos = atomicAdd(&g_cursor[e], 1);
    g_perm[pos] = t;
}

// ---------------- launch ----------------
extern "C" void kernel_launch(void* const* d_in, const int* in_sizes, int n_in,
                              void* d_out, int out_size)
{
    const float* x   = (const float*)d_in[0];
    const float* Wr1 = (const float*)d_in[1];
    const float* br1 = (const float*)d_in[2];
    const float* Wr2 = (const float*)d_in[3];
    const float* br2 = (const float*)d_in[4];
    const float* W1  = (const float*)d_in[5];
    const float* b1  = (const float*)d_in[6];
    const float* W2  = (const float*)d_in[7];
    const float* b2  = (const float*)d_in[8];
    float* out = (float*)d_out;

    // FFN1: A = x (gather), C = g_hidden (device symbol, DST_HIDDEN)
    auto* kFfn1 = ffn_mma<HID, EMB, true, true, false, false, true>;
    // FFN2: A = g_hidden (device symbol, SRC_HIDDEN), C = out (scatter)
    auto* kFfn2 = ffn_mma<EMB, HID, false, false, true, true, false>;
    cudaFuncSetAttribute(kFfn1, cudaFuncAttributeMaxDynamicSharedMemorySize, FFN_SMEM);
    cudaFuncSetAttribute(kFfn2, cudaFuncAttributeMaxDynamicSharedMemorySize, FFN_SMEM);

    init_counts<<<1, 32>>>();
    sgemm_router<<<dim3(N_TOK / 128, EMB / 128), 256>>>(x, Wr1, br1);
    router_argmax<<<(N_TOK * 32) / 256, 256>>>(Wr2, br2);
    scan_offsets<<<1, 1>>>();
    scatter_tokens<<<N_TOK / 256, 256>>>();
    kFfn1<<<dim3(N_TOK / 128, HID / 128, NE), 256, FFN_SMEM>>>(x, W1, b1, nullptr);
    kFfn2<<<dim3(N_TOK / 128, EMB / 128, NE), 256, FFN_SMEM>>>(nullptr, W2, b2, out);
}